// round 16
// baseline (speedup 1.0000x reference)
#include <cuda_runtime.h>
#include <math.h>

// Problem constants (match reference hyperparameters)
#define BB 8
#define HH 320
#define WW 1024
#define NPIX (BB * HH * WW)          // 2,621,440 per plane
#define NOFF 105                      // (2*7+1)*(2*3+1) search offsets
#define RR 20                         // sense radius
#define KDIM 41
#define KROWS 55                      // padded rows: dy in [-27, 27]
#define KPAD (KROWS * KDIM)           // 2255
#define KPAD2 2256                    // padded even
#define TX 32                         // tiles in x (1024/32)
#define TY 10                         // bin rows (320/32)
#define TY2 5                         // splat tile rows (320/64)
#define NBINS (BB * TY * TX)          // 2560
#define CAP 256                       // >= 144 provable max points/bin
#define WCAP 512                      // provable max per warp band list
#define WPR 32                        // mask words per row (1024/32)
#define MWORDS (BB * HH * WPR)        // 81920 words per map

// Scratch (device globals; no allocation allowed)
__device__ unsigned int       g_msrc[MWORDS];       // src bitmask
__device__ unsigned int       g_mdst[MWORDS];       // dst bitmask
__device__ unsigned int       g_upts[NBINS * CAP];  // packed points
__device__ int                g_cnt[NBINS];
__device__ unsigned long long g_Kdup[KPAD2];        // (w,w) duplicated pairs
__device__ int2               g_voff[NOFF];         // offsets by rank
__device__ unsigned char      g_rank[NOFF];         // window bit pos -> rank

#define MASK_BLOCKS (2 * NPIX / 16 / 256)   // 1280 (16 px/thread)
#define TAB_BLOCKS  10                       // covers max(NBINS, KPAD2)

// ---------------------------------------------------------------------------
// K0: build bitmasks (16 px/thread: 4x float4 -> 16-bit half -> shfl-or),
//     zero bins, build duplicated padded table + rank/offset tables.
// ---------------------------------------------------------------------------
__global__ void __launch_bounds__(256) bn_init(const float* __restrict__ src,
                                               const float* __restrict__ dst,
                                               const float* __restrict__ offx,
                                               const float* __restrict__ offy) {
    if (blockIdx.x < MASK_BLOCKS) {
        int gid = blockIdx.x * 256 + threadIdx.x;   // 16-px group id
        const float* p; unsigned* q; int o = gid;
        if (o < NPIX / 16) { p = src; q = g_msrc; }
        else               { o -= NPIX / 16; p = dst; q = g_mdst; }
        const float4* pv = (const float4*)p + (size_t)o * 4;
        float4 v0 = __ldg(pv), v1 = __ldg(pv + 1), v2 = __ldg(pv + 2), v3 = __ldg(pv + 3);
        unsigned h =  (v0.x > 0.5f ? 1u : 0u)     | (v0.y > 0.5f ? 2u : 0u)
                   |  (v0.z > 0.5f ? 4u : 0u)     | (v0.w > 0.5f ? 8u : 0u)
                   |  (v1.x > 0.5f ? 16u : 0u)    | (v1.y > 0.5f ? 32u : 0u)
                   |  (v1.z > 0.5f ? 64u : 0u)    | (v1.w > 0.5f ? 128u : 0u)
                   |  (v2.x > 0.5f ? 256u : 0u)   | (v2.y > 0.5f ? 512u : 0u)
                   |  (v2.z > 0.5f ? 1024u : 0u)  | (v2.w > 0.5f ? 2048u : 0u)
                   |  (v3.x > 0.5f ? 4096u : 0u)  | (v3.y > 0.5f ? 8192u : 0u)
                   |  (v3.z > 0.5f ? 16384u : 0u) | (v3.w > 0.5f ? 32768u : 0u);
        unsigned val = h << (16 * (o & 1));
        val |= __shfl_xor_sync(0xffffffffu, val, 1);
        if ((o & 1) == 0) q[o >> 1] = val;
        return;
    }
    int i = (blockIdx.x - MASK_BLOCKS) * 256 + threadIdx.x;
    if (i < NBINS) g_cnt[i] = 0;
    if (i < KPAD2) {
        int row = i / KDIM, col = i - row * KDIM;
        int dy = row - 27, dx = col - RR;
        float w = 0.0f;
        if (dy >= -RR && dy <= RR) {
            float d = sqrtf((float)(dx * dx + dy * dy));
            w = 0.7f * expf(-d * 1.9f / 24.0f);
        }
        unsigned wu = __float_as_uint(w);
        g_Kdup[i] = ((unsigned long long)wu << 32) | wu;
    }
    if (i < NOFF) {
        int ox = (int)offx[i], oy = (int)offy[i];
        g_voff[i] = make_int2(ox, oy);
        g_rank[(oy + 3) * 15 + (ox + 7)] = (unsigned char)i;
    }
}

// ---------------------------------------------------------------------------
// extract 32 bits starting at column c0 of a mask row (0 outside [0,1024))
// ---------------------------------------------------------------------------
__device__ __forceinline__ unsigned ex32(const unsigned* __restrict__ row, int c0) {
    int w0 = c0 >> 5;            // arithmetic shift: -1 for negative c0
    int sh = c0 & 31;
    unsigned a = ((unsigned)w0 < WPR) ? __ldg(row + w0) : 0u;
    unsigned b = ((unsigned)(w0 + 1) < WPR) ? __ldg(row + w0 + 1) : 0u;
    return __funnelshift_r(a, b, sh);
}

// ---------------------------------------------------------------------------
// K1: mask-based sparsify + ordered search. 8 px/thread. Pixels with m=0
//     contribute exact zeros to all 4 planes -> fast path stores constants.
//     Point packing: x[0:10) | y[10:19) | (vx+7)[19:23) | (vy+3)[23:26)
// ---------------------------------------------------------------------------
__global__ void __launch_bounds__(256) bn_match(float* __restrict__ out) {
    __shared__ unsigned char s_rank[NOFF];
    __shared__ int2          s_off[NOFF];
    int t = threadIdx.x;
    if (t < NOFF) { s_rank[t] = g_rank[t]; s_off[t] = g_voff[t]; }
    __syncthreads();

    int q = blockIdx.x * 256 + t;            // octet index
    int idx = q << 3;
    int x0 = idx & (WW - 1);
    int y  = (idx / WW) % HH;
    int b  = idx / (WW * HH);

    const unsigned* MS = g_msrc + (size_t)b * HH * WPR;
    const unsigned* MD = g_mdst + (size_t)b * HH * WPR;

    unsigned own = __ldg(MS + y * WPR + (x0 >> 5));
    unsigned bits8 = (own >> (x0 & 31)) & 255u;

    if (bits8 == 0) {
        // all 8 pixels: m = 0 -> all four planes exactly zero
        float4 z = make_float4(0.f, 0.f, 0.f, 0.f);
        #pragma unroll
        for (int pl = 2; pl < 6; ++pl) {
            __stcs((float4*)(out + (size_t)pl * NPIX + idx), z);
            __stcs((float4*)(out + (size_t)pl * NPIX + idx + 4), z);
        }
        return;
    }

    float m[8], vx[8], vy[8];
    #pragma unroll
    for (int e = 0; e < 8; ++e) { m[e] = 0.f; vx[e] = 0.f; vy[e] = 0.f; }

    // sparsity rows (shared across the octet): window starts at x0-2
    int c0s = x0 - 2;
    unsigned rA = (y >= 2) ? ex32(MS + (y - 2) * WPR, c0s) : 0u;
    unsigned rB = (y >= 1) ? ex32(MS + (y - 1) * WPR, c0s) : 0u;
    unsigned rC = ex32(MS + y * WPR, c0s);
    // dst window rows (shared across the octet): start at x0-7
    int c0 = x0 - 7;
    unsigned r[7];
    #pragma unroll
    for (int j = 0; j < 7; ++j) {
        int Y = y + j - 3;
        r[j] = (Y >= 0 && Y < HH) ? ex32(MD + Y * WPR, c0) : 0u;
    }

    unsigned bb8 = bits8;
    while (bb8) {
        int e = __ffs(bb8) - 1; bb8 &= bb8 - 1;
        // raster-preceding neighbors within radius 2
        unsigned blocked = ((rA >> e) & 31u) | ((rB >> e) & 31u) | ((rC >> e) & 3u);
        if (blocked) continue;
        // build 105-bit window (7 rows x 15 bits), bit G = row*15 + col
        unsigned long long lo, hi;
        {
            unsigned w0_ = (r[0] >> e) & 0x7FFFu, w1_ = (r[1] >> e) & 0x7FFFu,
                     w2_ = (r[2] >> e) & 0x7FFFu, w3_ = (r[3] >> e) & 0x7FFFu,
                     w4_ = (r[4] >> e) & 0x7FFFu, w5_ = (r[5] >> e) & 0x7FFFu,
                     w6_ = (r[6] >> e) & 0x7FFFu;
            lo = (unsigned long long)w0_
               | ((unsigned long long)w1_ << 15)
               | ((unsigned long long)w2_ << 30)
               | ((unsigned long long)w3_ << 45)
               | ((unsigned long long)(w4_ & 0xFu) << 60);
            hi = (unsigned long long)(w4_ >> 4)
               | ((unsigned long long)w5_ << 11)
               | ((unsigned long long)w6_ << 26);
        }
        // nearest hit = min rank over set bits
        int rmin = 255;
        unsigned long long mm = lo;
        while (mm) {
            int g = __ffsll(mm) - 1; mm &= mm - 1;
            int rk = s_rank[g]; rmin = rk < rmin ? rk : rmin;
        }
        mm = hi;
        while (mm) {
            int g = __ffsll(mm) - 1; mm &= mm - 1;
            int rk = s_rank[64 + g]; rmin = rk < rmin ? rk : rmin;
        }
        if (rmin < 255) {
            int2 o = s_off[rmin];
            m[e] = 1.0f; vx[e] = (float)o.x; vy[e] = (float)o.y;
            int x = x0 + e;
            int bin = (b * TY + (y >> 5)) * TX + (x >> 5);
            int pos = atomicAdd(&g_cnt[bin], 1);
            if (pos < CAP) {
                g_upts[bin * CAP + pos] = (unsigned)x
                    | ((unsigned)y << 10)
                    | ((unsigned)(o.x + 7) << 19)
                    | ((unsigned)(o.y + 3) << 23);
            }
        }
    }

    float yf = (float)y;
    #pragma unroll
    for (int g4 = 0; g4 < 2; ++g4) {
        float4 ox, oy, cx, cy;
        float* oxp = (float*)&ox; float* oyp = (float*)&oy;
        float* cxp = (float*)&cx; float* cyp = (float*)&cy;
        #pragma unroll
        for (int e = 0; e < 4; ++e) {
            int ee = g4 * 4 + e;
            float xf = (float)(x0 + ee);
            oxp[e] = xf * m[ee];
            oyp[e] = yf * m[ee];
            cxp[e] = (xf + vx[ee]) * m[ee];
            cyp[e] = (yf + vy[ee]) * m[ee];
        }
        int o4 = idx + g4 * 4;
        __stcs((float4*)(out + 2 * (size_t)NPIX + o4), ox);   // orgpts_x
        __stcs((float4*)(out + 3 * (size_t)NPIX + o4), oy);   // orgpts_y
        __stcs((float4*)(out + 4 * (size_t)NPIX + o4), cx);   // correspts_x
        __stcs((float4*)(out + 5 * (size_t)NPIX + o4), cy);   // correspts_y
    }
}

// ---------------------------------------------------------------------------
// K2: sparse gather "conv". One block = one 32x64 tile, 256 threads.
//     Warp w: rows 8w..8w+7, lane = column. 12-bin (4x3) neighborhood.
//     Lane-parallel band+x compaction (ballot) into per-warp smem list.
//     Accumulate: LDS.64 pair table + add.f32x2 + fma.f32x2 per row.
//     Compacted: (rx+32)[0:8) | (ry+32)[8:16) | (vx+7)[16:20) | (vy+3)[20:23)
// ---------------------------------------------------------------------------
__global__ void __launch_bounds__(256) bn_splat(float* __restrict__ out) {
    __shared__ ulonglong2   sKd2[KPAD2 / 2];   // (w,w) packed pairs
    __shared__ unsigned int s_list[8][WCAP];

    int t = threadIdx.x;
    {
        const ulonglong2* gv = (const ulonglong2*)g_Kdup;
        for (int i = t; i < KPAD2 / 2; i += 256) sKd2[i] = __ldg(gv + i);
    }
    const unsigned long long* sKd = (const unsigned long long*)sKd2;

    int blk = blockIdx.x;
    int tx  = blk % TX;
    int ty2 = (blk / TX) % TY2;
    int b   = blk / (TX * TY2);
    int gx0 = tx << 5, gy0 = ty2 << 6;

    int w    = t >> 5;
    int lane = t & 31;
    int ybase = w << 3;            // warp's first row within tile

    // prefetch the 12 bin counts lane-parallel
    int cnt_l = 0, bin_l = 0;
    if (lane < 12) {
        int nty = (ty2 << 1) + lane / 3 - 1, ntx = tx + lane % 3 - 1;
        if (nty >= 0 && nty < TY && ntx >= 0 && ntx < TX) {
            bin_l = (b * TY + nty) * TX + ntx;
            int c = __ldg(&g_cnt[bin_l]);
            cnt_l = c > CAP ? CAP : c;
        }
    }

    // ---- per-warp lane-parallel band + x compaction ----
    int n = 0;
    #pragma unroll
    for (int k = 0; k < 12; ++k) {
        int cnt = __shfl_sync(0xffffffffu, cnt_l, k);
        int bin = __shfl_sync(0xffffffffu, bin_l, k);
        for (int j0 = 0; j0 < cnt; j0 += 32) {
            int j = j0 + lane;
            bool valid = false;
            unsigned pk = 0;
            if (j < cnt) {
                unsigned u = __ldg(&g_upts[bin * CAP + j]);
                int rx = (int)(u & 1023u) - gx0;
                int ry = (int)((u >> 10) & 511u) - gy0;
                int d0 = ry - ybase;
                if (d0 >= -RR && d0 <= RR + 7 && rx >= -RR && rx <= 31 + RR) {
                    valid = true;
                    pk = (unsigned)(rx + 32)
                       | ((unsigned)(ry + 32) << 8)
                       | (((u >> 19) & 0x7Fu) << 16);
                }
            }
            unsigned ball = __ballot_sync(0xffffffffu, valid);
            int pos = n + __popc(ball & ((1u << lane) - 1u));
            if (valid && pos < WCAP) s_list[w][pos] = pk;
            n += __popc(ball);
        }
    }
    if (n > WCAP) n = WCAP;
    __syncthreads();   // sKd ready (own-warp list needs no sync)

    // ---- accumulate (packed f32x2) ----
    unsigned long long A0[8], A12[8];   // A0 = (a0, a0); A12 = (a1, a2)
    #pragma unroll
    for (int i = 0; i < 8; ++i) { A0[i] = 0ull; A12[i] = 0ull; }

    for (int j = 0; j < n; ++j) {
        unsigned pk = s_list[w][j];
        int rx = (int)(pk & 255u) - 32;
        int dx = rx - lane;
        if ((unsigned)(dx + RR) <= 2u * RR) {
            int ry = (int)((pk >> 8) & 255u) - 32;
            unsigned vxu = __float_as_uint((float)((int)((pk >> 16) & 15u) - 7));
            unsigned vyu = __float_as_uint((float)((int)((pk >> 20) & 7u) - 3));
            unsigned long long vxy;
            asm("mov.b64 %0, {%1, %2};" : "=l"(vxy) : "r"(vxu), "r"(vyu));
            // row for pixel i: dy = (ry - ybase) - i, padded index dy + 27
            int base = (ry - ybase + 27) * KDIM + dx + RR;
            #pragma unroll
            for (int i = 0; i < 8; ++i) {
                unsigned long long wp = sKd[base - i * KDIM];
                asm("add.rn.f32x2 %0, %0, %1;" : "+l"(A0[i]) : "l"(wp));
                asm("fma.rn.f32x2 %0, %1, %2, %0;" : "+l"(A12[i]) : "l"(wp), "l"(vxy));
            }
        }
    }

    #pragma unroll
    for (int i = 0; i < 8; ++i) {
        unsigned a0u, dummy, a1u, a2u;
        asm("mov.b64 {%0, %1}, %2;" : "=r"(a0u), "=r"(dummy) : "l"(A0[i]));
        asm("mov.b64 {%0, %1}, %2;" : "=r"(a1u), "=r"(a2u) : "l"(A12[i]));
        int gy = gy0 + ybase + i;
        size_t idx = ((size_t)b * HH + gy) * WW + gx0 + lane;
        float inv = 1.0f / (__uint_as_float(a0u) + 1.6f);    // ALPHA_PAD
        __stcs(out + idx,        (float)(gx0 + lane) + __uint_as_float(a1u) * inv); // morphedx
        __stcs(out + NPIX + idx, (float)gy           + __uint_as_float(a2u) * inv); // morphedy
    }
}

// ---------------------------------------------------------------------------
extern "C" void kernel_launch(void* const* d_in, const int* in_sizes, int n_in,
                              void* d_out, int out_size) {
    const float* src  = (const float*)d_in[0];   // binMapsrc [8,1,320,1024]
    const float* dst  = (const float*)d_in[1];   // binMapdst
    const float* offx = (const float*)d_in[2];   // xx [105]
    const float* offy = (const float*)d_in[3];   // yy [105]
    // d_in[4..7] = sxx, syy, cxx, cyy (constant grids; recomputed in closed form)
    float* out = (float*)d_out;                  // 6 planes of [8,320,1024]

    bn_init<<<MASK_BLOCKS + TAB_BLOCKS, 256>>>(src, dst, offx, offy);
    bn_match<<<(NPIX / 8) / 256, 256>>>(out);
    bn_splat<<<BB * TY2 * TX, 256>>>(out);
}

// round 17
// speedup vs baseline: 1.2312x; 1.2312x over previous
#include <cuda_runtime.h>
#include <math.h>

// Problem constants (match reference hyperparameters)
#define BB 8
#define HH 320
#define WW 1024
#define NPIX (BB * HH * WW)          // 2,621,440 per plane
#define NOFF 105                      // (2*7+1)*(2*3+1) search offsets
#define RR 20                         // sense radius
#define KDIM 41
#define KROWS 55                      // padded rows: dy in [-27, 27]
#define KPAD (KROWS * KDIM)           // 2255
#define KPAD2 2256                    // padded to multiple of 4
#define TX 32                         // tiles in x (1024/32)
#define TY 10                         // tile rows (320/32)
#define NBINS (BB * TY * TX)          // 2560
#define CAP 256                       // >= 144 provable max points/bin
#define WCAP 512                      // provable max per warp band list
#define WPR 32                        // mask words per row (1024/32)
#define MWORDS (BB * HH * WPR)        // 81920 words per map

// Scratch (device globals; no allocation allowed)
__device__ unsigned int  g_msrc[MWORDS];             // src bitmask
__device__ unsigned int  g_mdst[MWORDS];             // dst bitmask
__device__ unsigned int  g_upts[NBINS * CAP];        // packed points
__device__ int           g_cnt[NBINS];
__device__ __align__(16) float g_Kpad[KPAD2];        // pre-padded weight table
__device__ int2          g_voff[NOFF];               // offsets by rank
__device__ unsigned char g_rank[NOFF];               // window bit pos -> rank

#define MASK_BLOCKS (2 * NPIX / 8 / 256)   // 2560 (8 px/thread)
#define TAB_BLOCKS  12

// ---------------------------------------------------------------------------
// K0: build bitmasks (8 px/thread: float4 x2 -> nibble -> shfl-or), zero bins,
//     build padded table + rank/offset tables.
// ---------------------------------------------------------------------------
__global__ void __launch_bounds__(256) bn_init(const float* __restrict__ src,
                                               const float* __restrict__ dst,
                                               const float* __restrict__ offx,
                                               const float* __restrict__ offy) {
    if (blockIdx.x < MASK_BLOCKS) {
        int gid = blockIdx.x * 256 + threadIdx.x;   // octet id
        int lane = threadIdx.x & 31;
        const float* p; unsigned* q; int o = gid;
        if (o < NPIX / 8) { p = src; q = g_msrc; }
        else              { o -= NPIX / 8; p = dst; q = g_mdst; }
        float4 v0 = ((const float4*)p)[(size_t)o * 2];
        float4 v1 = ((const float4*)p)[(size_t)o * 2 + 1];
        unsigned nib =  (v0.x > 0.5f ? 1u : 0u)  | (v0.y > 0.5f ? 2u : 0u)
                     |  (v0.z > 0.5f ? 4u : 0u)  | (v0.w > 0.5f ? 8u : 0u)
                     |  (v1.x > 0.5f ? 16u : 0u) | (v1.y > 0.5f ? 32u : 0u)
                     |  (v1.z > 0.5f ? 64u : 0u) | (v1.w > 0.5f ? 128u : 0u);
        unsigned val = nib << (8 * (lane & 3));
        val |= __shfl_xor_sync(0xffffffffu, val, 1);
        val |= __shfl_xor_sync(0xffffffffu, val, 2);
        if ((lane & 3) == 0) q[o >> 2] = val;
        return;
    }
    int i = (blockIdx.x - MASK_BLOCKS) * 256 + threadIdx.x;
    if (i < NBINS) g_cnt[i] = 0;
    if (i < KPAD2) {
        int row = i / KDIM, col = i - row * KDIM;
        int dy = row - 27, dx = col - RR;
        float w = 0.0f;
        if (dy >= -RR && dy <= RR && i < KPAD) {
            float d = sqrtf((float)(dx * dx + dy * dy));
            w = 0.7f * expf(-d * 1.9f / 24.0f);
        }
        g_Kpad[i] = w;
    }
    if (i < NOFF) {
        int ox = (int)offx[i], oy = (int)offy[i];
        g_voff[i] = make_int2(ox, oy);
        g_rank[(oy + 3) * 15 + (ox + 7)] = (unsigned char)i;
    }
}

// ---------------------------------------------------------------------------
// extract 32 bits starting at column c0 of a mask row (0 outside [0,1024))
// ---------------------------------------------------------------------------
__device__ __forceinline__ unsigned ex32(const unsigned* __restrict__ row, int c0) {
    int w0 = c0 >> 5;            // arithmetic shift: -1 for negative c0
    int sh = c0 & 31;
    unsigned a = ((unsigned)w0 < WPR) ? __ldg(row + w0) : 0u;
    unsigned b = ((unsigned)(w0 + 1) < WPR) ? __ldg(row + w0 + 1) : 0u;
    return __funnelshift_r(a, b, sh);
}

// ---------------------------------------------------------------------------
// K1: mask-based sparsify + ordered search (set-bit iteration with rank min),
//     write 4 per-pixel planes (4 px/thread float4), append packed points.
//     Point packing: x[0:10) | y[10:19) | (vx+7)[19:23) | (vy+3)[23:26)
// ---------------------------------------------------------------------------
__global__ void __launch_bounds__(256) bn_match(float* __restrict__ out) {
    __shared__ unsigned char s_rank[NOFF];
    __shared__ int2          s_off[NOFF];
    int t = threadIdx.x;
    if (t < NOFF) { s_rank[t] = g_rank[t]; s_off[t] = g_voff[t]; }
    __syncthreads();

    int q = blockIdx.x * 256 + t;            // quad index
    int idx = q << 2;
    int x0 = idx & (WW - 1);
    int y  = (idx / WW) % HH;
    int b  = idx / (WW * HH);

    const unsigned* MS = g_msrc + (size_t)b * HH * WPR;
    const unsigned* MD = g_mdst + (size_t)b * HH * WPR;

    unsigned own = __ldg(MS + y * WPR + (x0 >> 5));
    unsigned bits4 = (own >> (x0 & 31)) & 15u;

    float m[4]  = {0, 0, 0, 0};
    float vx[4] = {0, 0, 0, 0};
    float vy[4] = {0, 0, 0, 0};

    if (bits4) {
        // sparsity rows (shared across the quad): window starts at x0-2
        int c0s = x0 - 2;
        unsigned rA = (y >= 2) ? ex32(MS + (y - 2) * WPR, c0s) : 0u;
        unsigned rB = (y >= 1) ? ex32(MS + (y - 1) * WPR, c0s) : 0u;
        unsigned rC = ex32(MS + y * WPR, c0s);
        // dst window rows (shared across the quad): start at x0-7
        int c0 = x0 - 7;
        unsigned r[7];
        #pragma unroll
        for (int j = 0; j < 7; ++j) {
            int Y = y + j - 3;
            r[j] = (Y >= 0 && Y < HH) ? ex32(MD + Y * WPR, c0) : 0u;
        }
        #pragma unroll
        for (int e = 0; e < 4; ++e) {
            if (!((bits4 >> e) & 1u)) continue;
            // raster-preceding neighbors within radius 2
            unsigned blocked = ((rA >> e) & 31u) | ((rB >> e) & 31u) | ((rC >> e) & 3u);
            if (blocked) continue;
            // build 105-bit window (7 rows x 15 bits), bit G = row*15 + col
            unsigned long long lo, hi;
            {
                unsigned w0_ = (r[0] >> e) & 0x7FFFu, w1_ = (r[1] >> e) & 0x7FFFu,
                         w2_ = (r[2] >> e) & 0x7FFFu, w3_ = (r[3] >> e) & 0x7FFFu,
                         w4_ = (r[4] >> e) & 0x7FFFu, w5_ = (r[5] >> e) & 0x7FFFu,
                         w6_ = (r[6] >> e) & 0x7FFFu;
                lo = (unsigned long long)w0_
                   | ((unsigned long long)w1_ << 15)
                   | ((unsigned long long)w2_ << 30)
                   | ((unsigned long long)w3_ << 45)
                   | ((unsigned long long)(w4_ & 0xFu) << 60);
                hi = (unsigned long long)(w4_ >> 4)
                   | ((unsigned long long)w5_ << 11)
                   | ((unsigned long long)w6_ << 26);
            }
            // nearest hit = min rank over set bits
            int rmin = 255;
            unsigned long long mm = lo;
            while (mm) {
                int g = __ffsll(mm) - 1; mm &= mm - 1;
                int rk = s_rank[g]; rmin = rk < rmin ? rk : rmin;
            }
            mm = hi;
            while (mm) {
                int g = __ffsll(mm) - 1; mm &= mm - 1;
                int rk = s_rank[64 + g]; rmin = rk < rmin ? rk : rmin;
            }
            if (rmin < 255) {
                int2 o = s_off[rmin];
                m[e] = 1.0f; vx[e] = (float)o.x; vy[e] = (float)o.y;
                int x = x0 + e;
                int bin = (b * TY + (y >> 5)) * TX + (x >> 5);
                int pos = atomicAdd(&g_cnt[bin], 1);
                if (pos < CAP) {
                    g_upts[bin * CAP + pos] = (unsigned)x
                        | ((unsigned)y << 10)
                        | ((unsigned)(o.x + 7) << 19)
                        | ((unsigned)(o.y + 3) << 23);
                }
            }
        }
    }

    float yf = (float)y;
    float4 ox, oy, cx, cy;
    float* oxp = (float*)&ox; float* oyp = (float*)&oy;
    float* cxp = (float*)&cx; float* cyp = (float*)&cy;
    #pragma unroll
    for (int e = 0; e < 4; ++e) {
        float xf = (float)(x0 + e);
        oxp[e] = xf * m[e];
        oyp[e] = yf * m[e];
        cxp[e] = (xf + vx[e]) * m[e];
        cyp[e] = (yf + vy[e]) * m[e];
    }
    *(float4*)(out + 2 * (size_t)NPIX + idx) = ox;   // orgpts_x
    *(float4*)(out + 3 * (size_t)NPIX + idx) = oy;   // orgpts_y
    *(float4*)(out + 4 * (size_t)NPIX + idx) = cx;   // correspts_x
    *(float4*)(out + 5 * (size_t)NPIX + idx) = cy;   // correspts_y
}

// ---------------------------------------------------------------------------
// K2: sparse gather "conv". One block = one 32x32 tile, 128 threads.
//     Warp w: rows 8w..8w+7, lane = column. Lane-parallel band+x compaction
//     (ballot) into per-warp smem list; SCALAR accumulate (LDS + FADD + 2 FFMA)
//     with pre-padded table staged via float4.
//     Compacted: (rx+32)[0:8) | (ry+32)[8:16) | (vx+7)[16:20) | (vy+3)[20:23)
// ---------------------------------------------------------------------------
__global__ void __launch_bounds__(128) bn_splat(float* __restrict__ out) {
    __shared__ __align__(16) float sKp[KPAD2];
    __shared__ unsigned int s_list[4][WCAP];

    int t = threadIdx.x;
    {
        const float4* gv = (const float4*)g_Kpad;
        float4* sv = (float4*)sKp;
        #pragma unroll
        for (int i = 0; i < KPAD2 / 4 / 128 + 1; ++i) {
            int j = t + i * 128;
            if (j < KPAD2 / 4) sv[j] = __ldg(gv + j);
        }
    }

    int blk = blockIdx.x;
    int tx = blk % TX;
    int ty = (blk / TX) % TY;
    int b  = blk / (TX * TY);
    int gx0 = tx << 5, gy0 = ty << 5;

    int w    = t >> 5;
    int lane = t & 31;
    int ybase = w << 3;            // warp's first row within tile

    // prefetch the 9 bin counts lane-parallel (kills serialized L2 chain)
    int cnt_l = 0, bin_l = 0;
    if (lane < 9) {
        int nty = ty + lane / 3 - 1, ntx = tx + lane % 3 - 1;
        if (nty >= 0 && nty < TY && ntx >= 0 && ntx < TX) {
            bin_l = (b * TY + nty) * TX + ntx;
            int c = __ldg(&g_cnt[bin_l]);
            cnt_l = c > CAP ? CAP : c;
        }
    }

    // ---- per-warp lane-parallel band + x compaction ----
    int n = 0;
    #pragma unroll
    for (int k = 0; k < 9; ++k) {
        int cnt = __shfl_sync(0xffffffffu, cnt_l, k);
        int bin = __shfl_sync(0xffffffffu, bin_l, k);
        for (int j0 = 0; j0 < cnt; j0 += 32) {
            int j = j0 + lane;
            bool valid = false;
            unsigned pk = 0;
            if (j < cnt) {
                unsigned u = __ldg(&g_upts[bin * CAP + j]);
                int rx = (int)(u & 1023u) - gx0;
                int ry = (int)((u >> 10) & 511u) - gy0;
                int d0 = ry - ybase;
                if (d0 >= -RR && d0 <= RR + 7 && rx >= -RR && rx <= 31 + RR) {
                    valid = true;
                    pk = (unsigned)(rx + 32)
                       | ((unsigned)(ry + 32) << 8)
                       | (((u >> 19) & 0x7Fu) << 16);
                }
            }
            unsigned ball = __ballot_sync(0xffffffffu, valid);
            int pos = n + __popc(ball & ((1u << lane) - 1u));
            if (valid && pos < WCAP) s_list[w][pos] = pk;
            n += __popc(ball);
        }
    }
    if (n > WCAP) n = WCAP;
    __syncthreads();   // sKp ready + own-warp list visibility

    // ---- accumulate (scalar: LDS + FADD + 2 FFMA per row) ----
    float a0[8], a1[8], a2[8];
    #pragma unroll
    for (int i = 0; i < 8; ++i) { a0[i] = 0.f; a1[i] = 0.f; a2[i] = 0.f; }

    for (int j = 0; j < n; ++j) {
        unsigned pk = s_list[w][j];
        int rx = (int)(pk & 255u) - 32;
        int dx = rx - lane;
        if ((unsigned)(dx + RR) <= 2u * RR) {
            int ry = (int)((pk >> 8) & 255u) - 32;
            float vxf = (float)((int)((pk >> 16) & 15u) - 7);
            float vyf = (float)((int)((pk >> 20) & 7u) - 3);
            // row for pixel i: dy = (ry - ybase) - i, padded index dy + 27
            int base = (ry - ybase + 27) * KDIM + dx + RR;
            #pragma unroll
            for (int i = 0; i < 8; ++i) {
                float wv = sKp[base - i * KDIM];
                a0[i] += wv;
                a1[i] += wv * vxf;
                a2[i] += wv * vyf;
            }
        }
    }

    #pragma unroll
    for (int i = 0; i < 8; ++i) {
        int gy = gy0 + ybase + i;
        size_t idx = ((size_t)b * HH + gy) * WW + gx0 + lane;
        float inv = 1.0f / (a0[i] + 1.6f);                    // ALPHA_PAD
        out[idx]        = (float)(gx0 + lane) + a1[i] * inv;  // morphedx
        out[NPIX + idx] = (float)gy           + a2[i] * inv;  // morphedy
    }
}

// ---------------------------------------------------------------------------
extern "C" void kernel_launch(void* const* d_in, const int* in_sizes, int n_in,
                              void* d_out, int out_size) {
    const float* src  = (const float*)d_in[0];   // binMapsrc [8,1,320,1024]
    const float* dst  = (const float*)d_in[1];   // binMapdst
    const float* offx = (const float*)d_in[2];   // xx [105]
    const float* offy = (const float*)d_in[3];   // yy [105]
    // d_in[4..7] = sxx, syy, cxx, cyy (constant grids; recomputed in closed form)
    float* out = (float*)d_out;                  // 6 planes of [8,320,1024]

    bn_init<<<MASK_BLOCKS + TAB_BLOCKS, 256>>>(src, dst, offx, offy);
    bn_match<<<(NPIX / 4) / 256, 256>>>(out);
    bn_splat<<<NBINS, 128>>>(out);
}